// round 15
// baseline (speedup 1.0000x reference)
#include <cuda_runtime.h>
#include <cuda_fp16.h>
#include <math.h>

#define RR       2336
#define CIN      4
#define COUT     16
#define NK       2
#define NTHREADS 768
#define NWARP    24
#define RPTF     3            // full j iterations (3*768 = 2304)
#define RPT      4
#define TAILN    32           // 2336 - 2304 (warp 0 only -> warp-uniform)
#define NB       1024
#define REDSZ    (NWARP * 17 + 24)

#define H2(x) (*(half2*)&(x))

// W as half: uint4 = 8 halves. Layout [k][i][h][r], h selects outputs h*8..h*8+7
__device__ uint4 g_Wh[NK * CIN * 2 * RR];
// staged per-(b,k) class norms
__device__ float g_cls[NB * NK];

__global__ void wtrans_kernel(const float* __restrict__ W) {
    int t = blockIdx.x * blockDim.x + threadIdx.x;
    if (t >= NK * CIN * 2 * RR) return;
    int r = t % RR;
    int q = t / RR;           // k*8 + i*2 + h
    int h = q & 1;
    int i = (q >> 1) & 3;
    int k = q >> 3;
    const float* s = W + (((size_t)(k * RR + r) * CIN + i) * COUT + h * 8);
    uint4 d;
    H2(d.x) = __floats2half2_rn(s[0], s[1]);
    H2(d.y) = __floats2half2_rn(s[2], s[3]);
    H2(d.z) = __floats2half2_rn(s[4], s[5]);
    H2(d.w) = __floats2half2_rn(s[6], s[7]);
    g_Wh[t] = d;
}

// 2-sync block reduction (ping-pong buffers make the guard sync unnecessary)
template <int N>
__device__ __forceinline__ void block_sum(float* v, float* red, int tid, int lane, int wid) {
#pragma unroll
    for (int n = 0; n < N; ++n) {
        float x = v[n];
#pragma unroll
        for (int off = 16; off > 0; off >>= 1)
            x += __shfl_xor_sync(0xffffffffu, x, off);
        v[n] = x;
    }
    if (lane == 0) {
#pragma unroll
        for (int n = 0; n < N; ++n) red[wid * N + n] = v[n];
    }
    __syncthreads();
    if (tid < N) {
        float t = red[tid];
#pragma unroll
        for (int w = 1; w < NWARP; ++w) t += red[w * N + tid];
        red[tid] = t;         // each combine lane owns its column
    }
    __syncthreads();
#pragma unroll
    for (int n = 0; n < N; ++n) v[n] = red[n];
}

__device__ __forceinline__ void squash16(const float* s, float* v) {
    float n0 = 0.f, n1 = 0.f;
#pragma unroll
    for (int o = 0; o < 8; ++o) {
        n0 = fmaf(s[o], s[o], n0);
        n1 = fmaf(s[o + 8], s[o + 8], n1);
    }
    float n = n0 + n1;
    float f = sqrtf(n) / (1.f + n);
#pragma unroll
    for (int o = 0; o < COUT; ++o) v[o] = s[o] * f;
}

__device__ __forceinline__ float dot16(const float* a, const float* b) {
    float d0 = 0.f, d1 = 0.f, d2 = 0.f, d3 = 0.f;
#pragma unroll
    for (int o = 0; o < 4; ++o) {
        d0 = fmaf(a[o],      b[o],      d0);
        d1 = fmaf(a[o + 4],  b[o + 4],  d1);
        d2 = fmaf(a[o + 8],  b[o + 8],  d2);
        d3 = fmaf(a[o + 12], b[o + 12], d3);
    }
    return (d0 + d1) + (d2 + d3);
}

// one block = one (batch, k) pair; u_ji tile in REGISTERS (half2)
__global__ __launch_bounds__(NTHREADS, 1)
void caps_kernel(const float* __restrict__ u) {
    extern __shared__ float sm[];
    float* red0 = sm;                  // ping-pong reduction buffers
    float* red1 = red0 + REDSZ;

    const int tid  = threadIdx.x;
    const int lane = tid & 31;
    const int wid  = tid >> 5;
    const int b    = blockIdx.x >> 1;
    const int k    = blockIdx.x & 1;
    const float4* up = (const float4*)(u + (size_t)b * RR * CIN);
    const bool tailok = (tid < TAILN);      // warp-uniform (warp 0 only)

    const uint4* Wk = g_Wh + k * (CIN * 2 * RR);

    // ===== Phase A: u_ji -> registers (half2); init route-sum folded in =====
    half2 tile[RPT][8];
    half2 ssh[8];
#pragma unroll
    for (int p = 0; p < 8; ++p) ssh[p] = __floats2half2_rn(0.f, 0.f);

#define ROUTE_A(JIDX, RVAL)                                                    \
    {                                                                          \
        const int r_ = (RVAL);                                                 \
        float4 a = up[r_];                                                     \
        half2 ah[4] = {__float2half2_rn(a.x), __float2half2_rn(a.y),           \
                       __float2half2_rn(a.z), __float2half2_rn(a.w)};          \
        half2 ac[8];                                                           \
        _Pragma("unroll")                                                      \
        for (int p = 0; p < 8; ++p) ac[p] = __floats2half2_rn(0.f, 0.f);       \
        _Pragma("unroll")                                                      \
        for (int i = 0; i < 4; ++i) {                                          \
            uint4 w0 = Wk[(i * 2 + 0) * RR + r_];                              \
            uint4 w1 = Wk[(i * 2 + 1) * RR + r_];                              \
            ac[0] = __hfma2(ah[i], H2(w0.x), ac[0]);                           \
            ac[1] = __hfma2(ah[i], H2(w0.y), ac[1]);                           \
            ac[2] = __hfma2(ah[i], H2(w0.z), ac[2]);                           \
            ac[3] = __hfma2(ah[i], H2(w0.w), ac[3]);                           \
            ac[4] = __hfma2(ah[i], H2(w1.x), ac[4]);                           \
            ac[5] = __hfma2(ah[i], H2(w1.y), ac[5]);                           \
            ac[6] = __hfma2(ah[i], H2(w1.z), ac[6]);                           \
            ac[7] = __hfma2(ah[i], H2(w1.w), ac[7]);                           \
        }                                                                      \
        _Pragma("unroll")                                                      \
        for (int p = 0; p < 8; ++p) {                                          \
            tile[JIDX][p] = ac[p];                                             \
            ssh[p] = __hadd2(ssh[p], ac[p]);                                   \
        }                                                                      \
    }

#pragma unroll
    for (int j = 0; j < RPTF; ++j)
        ROUTE_A(j, tid + j * NTHREADS)
    if (tailok) {
        ROUTE_A(RPTF, tid + RPTF * NTHREADS)
    } else {
#pragma unroll
        for (int p = 0; p < 8; ++p) tile[RPTF][p] = __floats2half2_rn(0.f, 0.f);
    }

    // ===== init reduction + squash (fp32) =====
    float v[COUT], vs[COUT];
    {
        float ss[COUT];
#pragma unroll
        for (int p = 0; p < 8; ++p) {
            float2 f = __half22float2(ssh[p]);
            ss[2 * p] = f.x; ss[2 * p + 1] = f.y;
        }
        block_sum<COUT>(ss, red0, tid, lane, wid);
#pragma unroll
        for (int o = 0; o < COUT; ++o) ss[o] *= (1.f / RR);
        squash16(ss, v);
#pragma unroll
        for (int o = 0; o < COUT; ++o) vs[o] = v[o];   // vsum = v0
    }

    // ===== 2 fused routing iterations on register tile =====
    // weight at iteration it is exp(u . vsum_it), vsum_1 = v0, vsum_2 = v0+v1
#pragma unroll
    for (int it = 0; it < 2; ++it) {
        half2 vh[8];
#pragma unroll
        for (int p = 0; p < 8; ++p)
            vh[p] = __floats2half2_rn(vs[2 * p], vs[2 * p + 1]);
        half2 ach[8];
#pragma unroll
        for (int p = 0; p < 8; ++p) ach[p] = __floats2half2_rn(0.f, 0.f);
        float accw = 0.f;

#define SWEEP(JIDX)                                                            \
        {                                                                      \
            half2 dpA = __hmul2(tile[JIDX][0], vh[0]);                         \
            half2 dpB = __hmul2(tile[JIDX][1], vh[1]);                         \
            dpA = __hfma2(tile[JIDX][2], vh[2], dpA);                          \
            dpB = __hfma2(tile[JIDX][3], vh[3], dpB);                          \
            dpA = __hfma2(tile[JIDX][4], vh[4], dpA);                          \
            dpB = __hfma2(tile[JIDX][5], vh[5], dpB);                          \
            dpA = __hfma2(tile[JIDX][6], vh[6], dpA);                          \
            dpB = __hfma2(tile[JIDX][7], vh[7], dpB);                          \
            float2 dfA = __half22float2(dpA);                                  \
            float2 dfB = __half22float2(dpB);                                  \
            float d = (dfA.x + dfA.y) + (dfB.x + dfB.y);                       \
            float w = __expf(d);                                               \
            accw += w;                                                         \
            half2 wh = __float2half2_rn(w);                                    \
            _Pragma("unroll")                                                  \
            for (int p = 0; p < 8; ++p)                                        \
                ach[p] = __hfma2(wh, tile[JIDX][p], ach[p]);                   \
        }

#pragma unroll
        for (int j = 0; j < RPTF; ++j)
            SWEEP(j)
        if (tailok)
            SWEEP(RPTF)

        float av[COUT + 1];
#pragma unroll
        for (int p = 0; p < 8; ++p) {
            float2 f = __half22float2(ach[p]);
            av[2 * p] = f.x; av[2 * p + 1] = f.y;
        }
        av[COUT] = accw;

        block_sum<COUT + 1>(av, (it == 0) ? red1 : red0, tid, lane, wid);

        float invZ = 1.f / av[COUT];
        float s[COUT];
#pragma unroll
        for (int o = 0; o < COUT; ++o) s[o] = av[o] * invZ;
        squash16(s, v);
#pragma unroll
        for (int o = 0; o < COUT; ++o) vs[o] += v[o];  // vsum for next sweep
    }

    if (tid == 0)
        g_cls[blockIdx.x] = sqrtf(dot16(v, v));   // blockIdx.x == b*2 + k

#undef ROUTE_A
#undef SWEEP
}

// epilogue: 2-way softmax per batch
__global__ void softmax_kernel(float* __restrict__ out) {
    int t = blockIdx.x * blockDim.x + threadIdx.x;
    if (t >= NB) return;
    float c0 = g_cls[2 * t + 0];
    float c1 = g_cls[2 * t + 1];
    float m = fmaxf(c0, c1);
    float e0 = __expf(c0 - m), e1 = __expf(c1 - m);
    float inv = 1.f / (e0 + e1);
    out[2 * t + 0] = e0 * inv;
    out[2 * t + 1] = e1 * inv;
}

extern "C" void kernel_launch(void* const* d_in, const int* in_sizes, int n_in,
                              void* d_out, int out_size) {
    const float* u = (const float*)d_in[0];   // [1024, 2336, 4]
    const float* W = (const float*)d_in[1];   // [2, 2336, 4, 16]
    float* out = (float*)d_out;               // [1024, 2]

    const int wtotal = NK * CIN * 2 * RR;
    wtrans_kernel<<<(wtotal + 255) / 256, 256>>>(W);

    const int smem_bytes = 2 * REDSZ * sizeof(float);
    caps_kernel<<<NB * NK, NTHREADS, smem_bytes>>>(u);

    softmax_kernel<<<(NB + 255) / 256, 256>>>(out);
}

// round 16
// speedup vs baseline: 1.1990x; 1.1990x over previous
#include <cuda_runtime.h>
#include <cuda_fp16.h>
#include <math.h>

#define RR       2336
#define CIN      4
#define COUT     16
#define NK       2
#define NTHREADS 512
#define NWARP    16
#define RPTF     4            // full j iterations (4*512 = 2048)
#define RPT      5
#define TAILN    288          // 2336 - 2048 (9 full warps -> warp-uniform tail)
#define NB       1024
#define REDSZ    (NWARP * 17 + 24)

#define H2(x) (*(half2*)&(x))

// W as half: uint4 = 8 halves. Layout [k][i][h][r], h selects outputs h*8..h*8+7
__device__ uint4 g_Wh[NK * CIN * 2 * RR];
// staged per-(b,k) class norms
__device__ float g_cls[NB * NK];

__global__ void wtrans_kernel(const float* __restrict__ W) {
    int t = blockIdx.x * blockDim.x + threadIdx.x;
    if (t >= NK * CIN * 2 * RR) return;
    int r = t % RR;
    int q = t / RR;           // k*8 + i*2 + h
    int h = q & 1;
    int i = (q >> 1) & 3;
    int k = q >> 3;
    const float* s = W + (((size_t)(k * RR + r) * CIN + i) * COUT + h * 8);
    uint4 d;
    H2(d.x) = __floats2half2_rn(s[0], s[1]);
    H2(d.y) = __floats2half2_rn(s[2], s[3]);
    H2(d.z) = __floats2half2_rn(s[4], s[5]);
    H2(d.w) = __floats2half2_rn(s[6], s[7]);
    g_Wh[t] = d;
}

// 2-sync block reduction (ping-pong buffers make the guard sync unnecessary)
template <int N>
__device__ __forceinline__ void block_sum(float* v, float* red, int tid, int lane, int wid) {
#pragma unroll
    for (int n = 0; n < N; ++n) {
        float x = v[n];
#pragma unroll
        for (int off = 16; off > 0; off >>= 1)
            x += __shfl_xor_sync(0xffffffffu, x, off);
        v[n] = x;
    }
    if (lane == 0) {
#pragma unroll
        for (int n = 0; n < N; ++n) red[wid * N + n] = v[n];
    }
    __syncthreads();
    if (tid < N) {
        float t = red[tid];
#pragma unroll
        for (int w = 1; w < NWARP; ++w) t += red[w * N + tid];
        red[tid] = t;         // each combine lane owns its column
    }
    __syncthreads();
#pragma unroll
    for (int n = 0; n < N; ++n) v[n] = red[n];
}

__device__ __forceinline__ void squash16(const float* s, float* v) {
    float n0 = 0.f, n1 = 0.f;
#pragma unroll
    for (int o = 0; o < 8; ++o) {
        n0 = fmaf(s[o], s[o], n0);
        n1 = fmaf(s[o + 8], s[o + 8], n1);
    }
    float n = n0 + n1;
    float f = sqrtf(n) / (1.f + n);
#pragma unroll
    for (int o = 0; o < COUT; ++o) v[o] = s[o] * f;
}

__device__ __forceinline__ float dot16(const float* a, const float* b) {
    float d0 = 0.f, d1 = 0.f, d2 = 0.f, d3 = 0.f;
#pragma unroll
    for (int o = 0; o < 4; ++o) {
        d0 = fmaf(a[o],      b[o],      d0);
        d1 = fmaf(a[o + 4],  b[o + 4],  d1);
        d2 = fmaf(a[o + 8],  b[o + 8],  d2);
        d3 = fmaf(a[o + 12], b[o + 12], d3);
    }
    return (d0 + d1) + (d2 + d3);
}

// one block = one (batch, k) pair; u_ji tile in REGISTERS (half2)
__global__ __launch_bounds__(NTHREADS, 1)
void caps_kernel(const float* __restrict__ u) {
    extern __shared__ float sm[];
    float* red0 = sm;                  // ping-pong reduction buffers
    float* red1 = red0 + REDSZ;

    const int tid  = threadIdx.x;
    const int lane = tid & 31;
    const int wid  = tid >> 5;
    const int b    = blockIdx.x >> 1;
    const int k    = blockIdx.x & 1;
    const float4* up = (const float4*)(u + (size_t)b * RR * CIN);
    const bool tailok = (tid < TAILN);      // warp-uniform

    const uint4* Wk = g_Wh + k * (CIN * 2 * RR);

    // ===== Phase A: u_ji -> registers (half2); init route-sum folded in =====
    half2 tile[RPT][8];
    half2 ssh[8];
#pragma unroll
    for (int p = 0; p < 8; ++p) ssh[p] = __floats2half2_rn(0.f, 0.f);

#define ROUTE_A(JIDX, RVAL)                                                    \
    {                                                                          \
        const int r_ = (RVAL);                                                 \
        float4 a = up[r_];                                                     \
        half2 ah[4] = {__float2half2_rn(a.x), __float2half2_rn(a.y),           \
                       __float2half2_rn(a.z), __float2half2_rn(a.w)};          \
        half2 ac[8];                                                           \
        _Pragma("unroll")                                                      \
        for (int p = 0; p < 8; ++p) ac[p] = __floats2half2_rn(0.f, 0.f);       \
        _Pragma("unroll")                                                      \
        for (int i = 0; i < 4; ++i) {                                          \
            uint4 w0 = Wk[(i * 2 + 0) * RR + r_];                              \
            uint4 w1 = Wk[(i * 2 + 1) * RR + r_];                              \
            ac[0] = __hfma2(ah[i], H2(w0.x), ac[0]);                           \
            ac[1] = __hfma2(ah[i], H2(w0.y), ac[1]);                           \
            ac[2] = __hfma2(ah[i], H2(w0.z), ac[2]);                           \
            ac[3] = __hfma2(ah[i], H2(w0.w), ac[3]);                           \
            ac[4] = __hfma2(ah[i], H2(w1.x), ac[4]);                           \
            ac[5] = __hfma2(ah[i], H2(w1.y), ac[5]);                           \
            ac[6] = __hfma2(ah[i], H2(w1.z), ac[6]);                           \
            ac[7] = __hfma2(ah[i], H2(w1.w), ac[7]);                           \
        }                                                                      \
        _Pragma("unroll")                                                      \
        for (int p = 0; p < 8; ++p) {                                          \
            tile[JIDX][p] = ac[p];                                             \
            ssh[p] = __hadd2(ssh[p], ac[p]);                                   \
        }                                                                      \
    }

#pragma unroll
    for (int j = 0; j < RPTF; ++j)
        ROUTE_A(j, tid + j * NTHREADS)
    if (tailok) {
        ROUTE_A(RPTF, tid + RPTF * NTHREADS)
    } else {
#pragma unroll
        for (int p = 0; p < 8; ++p) tile[RPTF][p] = __floats2half2_rn(0.f, 0.f);
    }

    // ===== init reduction + squash (fp32) =====
    float v[COUT], vs[COUT];
    {
        float ss[COUT];
#pragma unroll
        for (int p = 0; p < 8; ++p) {
            float2 f = __half22float2(ssh[p]);
            ss[2 * p] = f.x; ss[2 * p + 1] = f.y;
        }
        block_sum<COUT>(ss, red0, tid, lane, wid);
#pragma unroll
        for (int o = 0; o < COUT; ++o) ss[o] *= (1.f / RR);
        squash16(ss, v);
#pragma unroll
        for (int o = 0; o < COUT; ++o) vs[o] = v[o];   // vsum = v0
    }

    // ===== 2 fused routing iterations on register tile =====
    // weight at iteration it is exp(u . vsum_it), vsum_1 = v0, vsum_2 = v0+v1
#pragma unroll
    for (int it = 0; it < 2; ++it) {
        half2 vh[8];
#pragma unroll
        for (int p = 0; p < 8; ++p)
            vh[p] = __floats2half2_rn(vs[2 * p], vs[2 * p + 1]);
        half2 ach[8];
#pragma unroll
        for (int p = 0; p < 8; ++p) ach[p] = __floats2half2_rn(0.f, 0.f);
        float accw = 0.f;

#define SWEEP(JIDX)                                                            \
        {                                                                      \
            half2 dpA = __hmul2(tile[JIDX][0], vh[0]);                         \
            half2 dpB = __hmul2(tile[JIDX][1], vh[1]);                         \
            dpA = __hfma2(tile[JIDX][2], vh[2], dpA);                          \
            dpB = __hfma2(tile[JIDX][3], vh[3], dpB);                          \
            dpA = __hfma2(tile[JIDX][4], vh[4], dpA);                          \
            dpB = __hfma2(tile[JIDX][5], vh[5], dpB);                          \
            dpA = __hfma2(tile[JIDX][6], vh[6], dpA);                          \
            dpB = __hfma2(tile[JIDX][7], vh[7], dpB);                          \
            float2 dfA = __half22float2(dpA);                                  \
            float2 dfB = __half22float2(dpB);                                  \
            float d = (dfA.x + dfA.y) + (dfB.x + dfB.y);                       \
            float w = __expf(d);                                               \
            accw += w;                                                         \
            half2 wh = __float2half2_rn(w);                                    \
            _Pragma("unroll")                                                  \
            for (int p = 0; p < 8; ++p)                                        \
                ach[p] = __hfma2(wh, tile[JIDX][p], ach[p]);                   \
        }

#pragma unroll
        for (int j = 0; j < RPTF; ++j)
            SWEEP(j)
        if (tailok)
            SWEEP(RPTF)

        float av[COUT + 1];
#pragma unroll
        for (int p = 0; p < 8; ++p) {
            float2 f = __half22float2(ach[p]);
            av[2 * p] = f.x; av[2 * p + 1] = f.y;
        }
        av[COUT] = accw;

        block_sum<COUT + 1>(av, (it == 0) ? red1 : red0, tid, lane, wid);

        float invZ = 1.f / av[COUT];
        float s[COUT];
#pragma unroll
        for (int o = 0; o < COUT; ++o) s[o] = av[o] * invZ;
        squash16(s, v);
#pragma unroll
        for (int o = 0; o < COUT; ++o) vs[o] += v[o];  // vsum for next sweep
    }

    if (tid == 0)
        g_cls[blockIdx.x] = sqrtf(dot16(v, v));   // blockIdx.x == b*2 + k

#undef ROUTE_A
#undef SWEEP
}

// epilogue: 2-way softmax per batch
__global__ void softmax_kernel(float* __restrict__ out) {
    int t = blockIdx.x * blockDim.x + threadIdx.x;
    if (t >= NB) return;
    float c0 = g_cls[2 * t + 0];
    float c1 = g_cls[2 * t + 1];
    float m = fmaxf(c0, c1);
    float e0 = __expf(c0 - m), e1 = __expf(c1 - m);
    float inv = 1.f / (e0 + e1);
    out[2 * t + 0] = e0 * inv;
    out[2 * t + 1] = e1 * inv;
}

extern "C" void kernel_launch(void* const* d_in, const int* in_sizes, int n_in,
                              void* d_out, int out_size) {
    const float* u = (const float*)d_in[0];   // [1024, 2336, 4]
    const float* W = (const float*)d_in[1];   // [2, 2336, 4, 16]
    float* out = (float*)d_out;               // [1024, 2]

    const int wtotal = NK * CIN * 2 * RR;
    wtrans_kernel<<<(wtotal + 255) / 256, 256>>>(W);

    const int smem_bytes = 2 * REDSZ * sizeof(float);
    caps_kernel<<<NB * NK, NTHREADS, smem_bytes>>>(u);

    softmax_kernel<<<(NB + 255) / 256, 256>>>(out);
}